// round 12
// baseline (speedup 1.0000x reference)
#include <cuda_runtime.h>
#include <cstdint>

#define N_NODES 50000
#define N_EDGES 800000
#define D 96
#define SCAN_TILE 1024
#define NB ((N_NODES + SCAN_TILE - 1) / SCAN_TILE)   // 49

typedef unsigned long long ull;

// ---------------- device scratch (no allocations allowed) -------------------
__device__ int g_cnt[N_NODES];       // per-dst degree (histogram)
__device__ int g_rowptr[N_NODES];    // block-LOCAL exclusive scan of degrees
__device__ int g_pos[N_NODES];       // scatter cursors (block-local base)
__device__ int g_bsum[NB];           // per-scan-block totals
__device__ int g_bsumx[NB];          // exclusive scan of block totals
__device__ int g_csr_src[N_EDGES];   // src node per CSR slot
__device__ int g_scan_tick;          // block-completion counter (static 0)

// true rowptr[i] = g_rowptr[i] + g_bsumx[i >> 10]

// ---------------- packed f32x2 helpers --------------------------------------
__device__ __forceinline__ ull dup2(float a) {
    ull r; asm("mov.b64 %0, {%1, %1};" : "=l"(r) : "f"(a)); return r;
}
__device__ __forceinline__ void fma2(ull& d, ull a, ull b) {
    asm("fma.rn.f32x2 %0, %1, %2, %0;" : "+l"(d) : "l"(a), "l"(b));
}
__device__ __forceinline__ void fadd2(ull& d, ull a) {
    asm("add.rn.f32x2 %0, %0, %1;" : "+l"(d) : "l"(a));
}
__device__ __forceinline__ ull fmul2(ull a, ull b) {
    ull r; asm("mul.rn.f32x2 %0, %1, %2;" : "=l"(r) : "l"(a), "l"(b)); return r;
}

// ---------------------------------------------------------------------------
// K1: histogram of dst degrees (2 edges/thread, no rank store)
// ---------------------------------------------------------------------------
__global__ void k_hist(const int* __restrict__ ei) {
    int i = blockIdx.x * blockDim.x + threadIdx.x;
    int e = i * 2;
    if (e >= N_EDGES) return;
    int2 d2 = *reinterpret_cast<const int2*>(ei + N_EDGES + e);
    atomicAdd(&g_cnt[d2.x], 1);
    atomicAdd(&g_cnt[d2.y], 1);
}

// ---------------------------------------------------------------------------
// K2: per-block local exclusive scan; LAST block also scans the 49 block
//     totals into g_bsumx and resets the tick (replay-safe).
// ---------------------------------------------------------------------------
__global__ __launch_bounds__(256) void k_scan1() {
    __shared__ int wsum[8];
    __shared__ bool is_last;
    const int blk = blockIdx.x, t = threadIdx.x;
    const int lane = t & 31, wid = t >> 5;
    int idx = blk * SCAN_TILE + t * 4;
    int v[4];
    #pragma unroll
    for (int i = 0; i < 4; i++)
        v[i] = (idx + i < N_NODES) ? g_cnt[idx + i] : 0;
    int tsum = v[0] + v[1] + v[2] + v[3];

    int incl = tsum;
    #pragma unroll
    for (int off = 1; off < 32; off <<= 1) {
        int s = __shfl_up_sync(0xffffffffu, incl, off);
        if (lane >= off) incl += s;
    }
    if (lane == 31) wsum[wid] = incl;
    __syncthreads();
    if (t == 0) {
        int s = 0;
        #pragma unroll
        for (int i = 0; i < 8; i++) { int x = wsum[i]; wsum[i] = s; s += x; }
        g_bsum[blk] = s;
    }
    __syncthreads();
    int excl = wsum[wid] + (incl - tsum);
    #pragma unroll
    for (int i = 0; i < 4; i++) {
        if (idx + i < N_NODES) {
            g_rowptr[idx + i] = excl;
            g_pos[idx + i]    = excl;
        }
        excl += v[i];
    }

    // ---- last-block finalization: scan g_bsum -> g_bsumx ----
    __threadfence();
    if (t == 0) is_last = (atomicAdd(&g_scan_tick, 1) == NB - 1);
    __syncthreads();
    if (is_last && t == 0) {
        const volatile int* bs = g_bsum;
        int a = 0;
        #pragma unroll
        for (int i = 0; i < NB; i++) { int x = bs[i]; g_bsumx[i] = a; a += x; }
        g_scan_tick = 0;   // reset for next graph replay
        __threadfence();
    }
}

// ---------------------------------------------------------------------------
// K3: scatter src ids: slot = pos[dst]++ (+ bsumx[dst>>10])
// ---------------------------------------------------------------------------
__global__ void k_scatter(const int* __restrict__ ei) {
    int e = blockIdx.x * blockDim.x + threadIdx.x;
    if (e >= N_EDGES) return;
    int dst = ei[N_EDGES + e];
    int p = atomicAdd(&g_pos[dst], 1) + g_bsumx[dst >> 10];
    g_csr_src[p] = ei[e];
}

// ---------------------------------------------------------------------------
// K4: FUSED aggregation + linear + ReLU.
//   Per block of BM=128 nodes:
//     phase A: warp-per-node mean aggregation straight into As smem tile
//     GEMM1:   acc = bl + As(agg) @ Wl^T
//     restage: As <- x rows, Ws <- Wr
//     GEMM2:   acc += As(x) @ Wr^T ; ReLU ; store
//   256 threads, TM=8 x TN=6, packed fma.rn.f32x2, 2 CTAs/SM.
// ---------------------------------------------------------------------------
constexpr int BM = 128;
constexpr int BN = 96;
constexpr int TM = 8;
constexpr int TN = 6;
constexpr int LTHREADS = 256;
constexpr int WPAD = 98;
constexpr int SMEM_FLOATS = BM * D + D * WPAD + BN;
constexpr size_t SMEM_BYTES = (size_t)SMEM_FLOATS * sizeof(float);  // ~87 KB

__device__ __forceinline__ void gemm_core(const float* As, const float* Ws,
                                          int n0, int o0, ull acc[TM][3]) {
    for (int k = 0; k < D; k += 4) {
        ull w[4][3];
        #pragma unroll
        for (int kk = 0; kk < 4; kk++) {
            const float* wr = Ws + (k + kk) * WPAD + o0;
            w[kk][0] = *reinterpret_cast<const ull*>(wr);
            w[kk][1] = *reinterpret_cast<const ull*>(wr + 2);
            w[kk][2] = *reinterpret_cast<const ull*>(wr + 4);
        }
        #pragma unroll
        for (int i = 0; i < TM; i++) {
            float4 av = *reinterpret_cast<const float4*>(As + (n0 + i) * D + k);
            ull ax = dup2(av.x), ay = dup2(av.y), az = dup2(av.z), aw = dup2(av.w);
            fma2(acc[i][0], ax, w[0][0]); fma2(acc[i][1], ax, w[0][1]); fma2(acc[i][2], ax, w[0][2]);
            fma2(acc[i][0], ay, w[1][0]); fma2(acc[i][1], ay, w[1][1]); fma2(acc[i][2], ay, w[1][2]);
            fma2(acc[i][0], az, w[2][0]); fma2(acc[i][1], az, w[2][1]); fma2(acc[i][2], az, w[2][2]);
            fma2(acc[i][0], aw, w[3][0]); fma2(acc[i][1], aw, w[3][1]); fma2(acc[i][2], aw, w[3][2]);
        }
    }
}

__device__ __forceinline__ void stage_W(const float* __restrict__ W,
                                        float* Ws, int t) {
    for (int idx = t; idx < D * D; idx += LTHREADS) {
        int o = idx / D, k = idx - o * D;
        Ws[k * WPAD + o] = W[o * D + k];
    }
}

__global__ __launch_bounds__(LTHREADS, 2)
void k_fused(const float* __restrict__ x,
             const float* __restrict__ Wl,
             const float* __restrict__ bl,
             const float* __restrict__ Wr,
             float* __restrict__ out)
{
    extern __shared__ float smem[];
    float* As  = smem;               // [BM][96]
    float* Ws  = smem + BM * D;      // [96][WPAD]
    float* bls = Ws + D * WPAD;      // [BN]

    const int t = threadIdx.x;
    const int wid = t >> 5, lane = t & 31;
    const int rowBase = blockIdx.x * BM;
    if (t < BN) bls[t] = bl[t];

    // stage Ws with Wl (used by GEMM1)
    stage_W(Wl, Ws, t);

    // ---- phase A: aggregate 16 nodes per warp into As ----
    const bool act = lane < 24;
    const int col = lane * 4;
    for (int i = 0; i < BM / 8; i++) {
        int r = wid * (BM / 8) + i;
        int node = rowBase + r;
        ull a0 = 0, a1 = 0, b0 = 0, b1 = 0;
        int deg = 0;
        if (node < N_NODES) {
            int beg = g_rowptr[node] + g_bsumx[node >> 10];
            int end = (node + 1 < N_NODES)
                    ? (g_rowptr[node + 1] + g_bsumx[(node + 1) >> 10]) : N_EDGES;
            deg = end - beg;
            int j = beg;
            for (; j + 4 <= end; j += 4) {
                int s0 = __ldg(g_csr_src + j + 0);
                int s1 = __ldg(g_csr_src + j + 1);
                int s2 = __ldg(g_csr_src + j + 2);
                int s3 = __ldg(g_csr_src + j + 3);
                if (act) {
                    ulonglong2 v0 = *reinterpret_cast<const ulonglong2*>(x + (size_t)s0 * D + col);
                    ulonglong2 v1 = *reinterpret_cast<const ulonglong2*>(x + (size_t)s1 * D + col);
                    ulonglong2 v2 = *reinterpret_cast<const ulonglong2*>(x + (size_t)s2 * D + col);
                    ulonglong2 v3 = *reinterpret_cast<const ulonglong2*>(x + (size_t)s3 * D + col);
                    fadd2(a0, v0.x); fadd2(a1, v0.y);
                    fadd2(b0, v1.x); fadd2(b1, v1.y);
                    fadd2(a0, v2.x); fadd2(a1, v2.y);
                    fadd2(b0, v3.x); fadd2(b1, v3.y);
                }
            }
            for (; j < end; j++) {
                int s = __ldg(g_csr_src + j);
                if (act) {
                    ulonglong2 v = *reinterpret_cast<const ulonglong2*>(x + (size_t)s * D + col);
                    fadd2(a0, v.x); fadd2(a1, v.y);
                }
            }
        }
        fadd2(a0, b0); fadd2(a1, b1);
        float inv = (deg > 0) ? 1.0f / (float)deg : 0.0f;
        ull iv = dup2(inv);
        if (act) {
            ulonglong2 rr;
            rr.x = fmul2(a0, iv);
            rr.y = fmul2(a1, iv);
            *reinterpret_cast<ulonglong2*>(As + r * D + col) = rr;
        }
    }
    __syncthreads();

    const int cg = t & 15, rg = t >> 4;
    const int o0 = cg * TN, n0 = rg * TM;

    // ---- GEMM1: acc = bias + agg @ Wl^T ----
    ull acc[TM][3];
    {
        ull b0 = *reinterpret_cast<const ull*>(bls + o0);
        ull b1 = *reinterpret_cast<const ull*>(bls + o0 + 2);
        ull b2 = *reinterpret_cast<const ull*>(bls + o0 + 4);
        #pragma unroll
        for (int i = 0; i < TM; i++) { acc[i][0] = b0; acc[i][1] = b1; acc[i][2] = b2; }
    }
    gemm_core(As, Ws, n0, o0, acc);
    __syncthreads();

    // ---- restage: As <- x rows, Ws <- Wr ----
    stage_W(Wr, Ws, t);
    for (int idx = t; idx < BM * (D / 4); idx += LTHREADS) {
        int r = idx / (D / 4), q = idx - r * (D / 4);
        int node = rowBase + r;
        float4 v = make_float4(0.f, 0.f, 0.f, 0.f);
        if (node < N_NODES)
            v = *reinterpret_cast<const float4*>(x + (size_t)node * D + q * 4);
        *reinterpret_cast<float4*>(As + r * D + q * 4) = v;
    }
    __syncthreads();

    // ---- GEMM2: acc += x @ Wr^T ; ReLU ; store ----
    gemm_core(As, Ws, n0, o0, acc);

    #pragma unroll
    for (int i = 0; i < TM; i++) {
        int node = rowBase + n0 + i;
        if (node >= N_NODES) continue;
        float* dst = out + (size_t)node * D + o0;
        #pragma unroll
        for (int j = 0; j < 3; j++) {
            float lo, hi;
            asm("mov.b64 {%0, %1}, %2;" : "=f"(lo), "=f"(hi) : "l"(acc[i][j]));
            float2 r = make_float2(fmaxf(lo, 0.f), fmaxf(hi, 0.f));
            *reinterpret_cast<float2*>(dst + 2 * j) = r;
        }
    }
}

// ---------------------------------------------------------------------------
extern "C" void kernel_launch(void* const* d_in, const int* in_sizes, int n_in,
                              void* d_out, int out_size) {
    const float* x  = (const float*)d_in[0];   // [N, 96]
    const int* ei   = (const int*)d_in[1];     // [2, E]
    const float* Wl = (const float*)d_in[2];   // [96, 96]
    const float* bl = (const float*)d_in[3];   // [96]
    const float* Wr = (const float*)d_in[4];   // [96, 96]
    float* out = (float*)d_out;                // [N, 96]

    cudaFuncSetAttribute(k_fused, cudaFuncAttributeMaxDynamicSharedMemorySize,
                         (int)SMEM_BYTES);

    void* cnt_ptr = nullptr;
    cudaGetSymbolAddress(&cnt_ptr, g_cnt);
    cudaMemsetAsync(cnt_ptr, 0, sizeof(int) * N_NODES);

    k_hist<<<(N_EDGES / 2 + 255) / 256, 256>>>(ei);
    k_scan1<<<NB, 256>>>();
    k_scatter<<<(N_EDGES + 255) / 256, 256>>>(ei);
    k_fused<<<(N_NODES + BM - 1) / BM, LTHREADS, SMEM_BYTES>>>(x, Wl, bl, Wr, out);
}

// round 13
// speedup vs baseline: 1.5902x; 1.5902x over previous
#include <cuda_runtime.h>
#include <cstdint>

#define N_NODES 50000
#define N_EDGES 800000
#define D 96
#define SCAN_TILE 1024
#define NB ((N_NODES + SCAN_TILE - 1) / SCAN_TILE)   // 49

typedef unsigned long long ull;
typedef unsigned int uint32;

// ---------------- device scratch (no allocations allowed) -------------------
__device__ int g_cnt[N_NODES];       // per-dst degree (histogram)
__device__ int g_rowptr[N_NODES];    // block-LOCAL exclusive scan of degrees
__device__ int g_pos[N_NODES];       // scatter cursors (block-local base)
__device__ int g_bsum[NB];           // per-scan-block totals
__device__ int g_bsumx[NB];          // exclusive scan of block totals
__device__ int g_csr_src[N_EDGES];   // src node per CSR slot
__device__ int g_scan_tick;          // block-completion counter (static 0)

// true rowptr[i] = g_rowptr[i] + g_bsumx[i >> 10]

// ---------------- packed f32x2 helpers (aggregation) -------------------------
__device__ __forceinline__ ull dup2(float a) {
    ull r; asm("mov.b64 %0, {%1, %1};" : "=l"(r) : "f"(a)); return r;
}
__device__ __forceinline__ void fadd2(ull& d, ull a) {
    asm("add.rn.f32x2 %0, %0, %1;" : "+l"(d) : "l"(a));
}
__device__ __forceinline__ ull fmul2(ull a, ull b) {
    ull r; asm("mul.rn.f32x2 %0, %1, %2;" : "=l"(r) : "l"(a), "l"(b)); return r;
}

// ---------------------------------------------------------------------------
// K1: histogram of dst degrees (2 edges/thread)
// ---------------------------------------------------------------------------
__global__ void k_hist(const int* __restrict__ ei) {
    int i = blockIdx.x * blockDim.x + threadIdx.x;
    int e = i * 2;
    if (e >= N_EDGES) return;
    int2 d2 = *reinterpret_cast<const int2*>(ei + N_EDGES + e);
    atomicAdd(&g_cnt[d2.x], 1);
    atomicAdd(&g_cnt[d2.y], 1);
}

// ---------------------------------------------------------------------------
// K2: per-block local exclusive scan; LAST block scans the 49 block totals.
// ---------------------------------------------------------------------------
__global__ __launch_bounds__(256) void k_scan1() {
    __shared__ int wsum[8];
    __shared__ bool is_last;
    const int blk = blockIdx.x, t = threadIdx.x;
    const int lane = t & 31, wid = t >> 5;
    int idx = blk * SCAN_TILE + t * 4;
    int v[4];
    #pragma unroll
    for (int i = 0; i < 4; i++)
        v[i] = (idx + i < N_NODES) ? g_cnt[idx + i] : 0;
    int tsum = v[0] + v[1] + v[2] + v[3];

    int incl = tsum;
    #pragma unroll
    for (int off = 1; off < 32; off <<= 1) {
        int s = __shfl_up_sync(0xffffffffu, incl, off);
        if (lane >= off) incl += s;
    }
    if (lane == 31) wsum[wid] = incl;
    __syncthreads();
    if (t == 0) {
        int s = 0;
        #pragma unroll
        for (int i = 0; i < 8; i++) { int x = wsum[i]; wsum[i] = s; s += x; }
        g_bsum[blk] = s;
    }
    __syncthreads();
    int excl = wsum[wid] + (incl - tsum);
    #pragma unroll
    for (int i = 0; i < 4; i++) {
        if (idx + i < N_NODES) {
            g_rowptr[idx + i] = excl;
            g_pos[idx + i]    = excl;
        }
        excl += v[i];
    }

    __threadfence();
    if (t == 0) is_last = (atomicAdd(&g_scan_tick, 1) == NB - 1);
    __syncthreads();
    if (is_last && t == 0) {
        const volatile int* bs = g_bsum;
        int a = 0;
        #pragma unroll
        for (int i = 0; i < NB; i++) { int x = bs[i]; g_bsumx[i] = a; a += x; }
        g_scan_tick = 0;
        __threadfence();
    }
}

// ---------------------------------------------------------------------------
// K3: scatter src ids: slot = pos[dst]++ (+ bsumx[dst>>10])
// ---------------------------------------------------------------------------
__global__ void k_scatter(const int* __restrict__ ei) {
    int e = blockIdx.x * blockDim.x + threadIdx.x;
    if (e >= N_EDGES) return;
    int dst = ei[N_EDGES + e];
    int p = atomicAdd(&g_pos[dst], 1) + g_bsumx[dst >> 10];
    g_csr_src[p] = ei[e];
}

// ---------------------------------------------------------------------------
// K4: warp-per-node mean aggregation (R8-proven). Lanes 0..23 own a float4.
// ---------------------------------------------------------------------------
__global__ void k_agg(const float* __restrict__ x, float* __restrict__ out) {
    int gw = (blockIdx.x * blockDim.x + threadIdx.x) >> 5;
    if (gw >= N_NODES) return;
    int lane = threadIdx.x & 31;
    int beg = g_rowptr[gw] + g_bsumx[gw >> 10];
    int end = (gw + 1 < N_NODES)
            ? (g_rowptr[gw + 1] + g_bsumx[(gw + 1) >> 10]) : N_EDGES;

    const bool act = lane < 24;
    const int col = lane * 4;

    ull a0 = 0, a1 = 0, b0 = 0, b1 = 0;

    int j = beg;
    for (; j + 4 <= end; j += 4) {
        int s0 = __ldg(g_csr_src + j + 0);
        int s1 = __ldg(g_csr_src + j + 1);
        int s2 = __ldg(g_csr_src + j + 2);
        int s3 = __ldg(g_csr_src + j + 3);
        if (act) {
            ulonglong2 v0 = *reinterpret_cast<const ulonglong2*>(x + (size_t)s0 * D + col);
            ulonglong2 v1 = *reinterpret_cast<const ulonglong2*>(x + (size_t)s1 * D + col);
            ulonglong2 v2 = *reinterpret_cast<const ulonglong2*>(x + (size_t)s2 * D + col);
            ulonglong2 v3 = *reinterpret_cast<const ulonglong2*>(x + (size_t)s3 * D + col);
            fadd2(a0, v0.x); fadd2(a1, v0.y);
            fadd2(b0, v1.x); fadd2(b1, v1.y);
            fadd2(a0, v2.x); fadd2(a1, v2.y);
            fadd2(b0, v3.x); fadd2(b1, v3.y);
        }
    }
    for (; j < end; j++) {
        int s = __ldg(g_csr_src + j);
        if (act) {
            ulonglong2 v = *reinterpret_cast<const ulonglong2*>(x + (size_t)s * D + col);
            fadd2(a0, v.x); fadd2(a1, v.y);
        }
    }
    fadd2(a0, b0); fadd2(a1, b1);

    int deg = end - beg;
    float inv = (deg > 0) ? 1.0f / (float)deg : 0.0f;
    ull iv = dup2(inv);
    if (act) {
        ulonglong2 r;
        r.x = fmul2(a0, iv);
        r.y = fmul2(a1, iv);
        *reinterpret_cast<ulonglong2*>(out + (size_t)gw * D + col) = r;
    }
}

// ---------------------------------------------------------------------------
// K5: tf32 tensor-core linear + ReLU.
//   z = relu(agg @ Wl^T + x @ Wr^T + bl), via mma.sync.m16n8k8.tf32.
//   BM=128 rows/block, 128 threads (4 warps), warp = 2 m-tiles x 12 n-tiles.
//   Two K=96 halves: (agg, Wl) then (x, Wr), accumulated in C regs.
//   B-fragment of A@W^T is row-major W directly (B[k][o] = W[o][k]).
// ---------------------------------------------------------------------------
constexpr int APAD = 100;   // floats per smem row: conflict-free fragments
constexpr int LTHREADS = 128;
constexpr int SMEM_FLOATS = 128 * APAD + 96 * APAD + 96;
constexpr size_t SMEM_BYTES = (size_t)SMEM_FLOATS * sizeof(float);  // 89,984 B

__device__ __forceinline__ uint32 to_tf32(float f) {
    uint32 u;
    asm("cvt.rna.tf32.f32 %0, %1;" : "=r"(u) : "f"(f));
    return u;
}
__device__ __forceinline__ void mma_tf32(float c[4], const uint32 a[4],
                                         const uint32 b[2]) {
    asm("mma.sync.aligned.m16n8k8.row.col.f32.tf32.tf32.f32 "
        "{%0,%1,%2,%3}, {%4,%5,%6,%7}, {%8,%9}, {%0,%1,%2,%3};"
        : "+f"(c[0]), "+f"(c[1]), "+f"(c[2]), "+f"(c[3])
        : "r"(a[0]), "r"(a[1]), "r"(a[2]), "r"(a[3]), "r"(b[0]), "r"(b[1]));
}

__global__ __launch_bounds__(LTHREADS, 2)
void k_linear(const float* __restrict__ x,
              const float* __restrict__ Wl,
              const float* __restrict__ bl,
              const float* __restrict__ Wr,
              float* __restrict__ out)   // agg_mean on entry, z on exit
{
    extern __shared__ float smem[];
    float* As  = smem;                  // [128][APAD] tf32 bits
    float* Ws  = smem + 128 * APAD;     // [96][APAD]  tf32 bits
    float* bls = Ws + 96 * APAD;        // [96]

    const int t = threadIdx.x;
    const int warp = t >> 5, lane = t & 31;
    const int g = lane >> 2, tq = lane & 3;   // group row, quad col
    const int rowBase = blockIdx.x * 128;
    if (t < 96) bls[t] = bl[t];

    float c[2][12][4];
    #pragma unroll
    for (int m = 0; m < 2; m++)
        #pragma unroll
        for (int n = 0; n < 12; n++)
            #pragma unroll
            for (int q = 0; q < 4; q++) c[m][n][q] = 0.f;

    #pragma unroll
    for (int h = 0; h < 2; h++) {
        const float* W   = h ? Wr : Wl;
        const float* src = h ? x  : out;

        // ---- stage Ws[o][k] = tf32(W[o][k])  (coalesced along k)
        for (int idx = t; idx < D * D; idx += LTHREADS) {
            int o = idx / D, k = idx - o * D;
            *reinterpret_cast<uint32*>(Ws + o * APAD + k) = to_tf32(W[idx]);
        }
        // ---- stage As rows (float4 load, tf32 convert)
        for (int idx = t; idx < 128 * (D / 4); idx += LTHREADS) {
            int r = idx / (D / 4), q = idx - r * (D / 4);
            int node = rowBase + r;
            float4 v = make_float4(0.f, 0.f, 0.f, 0.f);
            if (node < N_NODES)
                v = *reinterpret_cast<const float4*>(src + (size_t)node * D + q * 4);
            uint32* dst = reinterpret_cast<uint32*>(As + r * APAD + q * 4);
            dst[0] = to_tf32(v.x); dst[1] = to_tf32(v.y);
            dst[2] = to_tf32(v.z); dst[3] = to_tf32(v.w);
        }
        __syncthreads();

        // ---- MMA mainloop: 12 k-steps of 8
        for (int kt = 0; kt < 12; kt++) {
            const int kb = kt * 8;
            uint32 a[2][4];
            #pragma unroll
            for (int m = 0; m < 2; m++) {
                const uint32* ap = reinterpret_cast<const uint32*>(
                    As + (warp * 32 + m * 16) * APAD + kb);
                a[m][0] = ap[(g)     * APAD + tq];
                a[m][1] = ap[(g + 8) * APAD + tq];
                a[m][2] = ap[(g)     * APAD + tq + 4];
                a[m][3] = ap[(g + 8) * APAD + tq + 4];
            }
            uint32 b[12][2];
            #pragma unroll
            for (int n = 0; n < 12; n++) {
                const uint32* bp = reinterpret_cast<const uint32*>(
                    Ws + (n * 8 + g) * APAD + kb);
                b[n][0] = bp[tq];
                b[n][1] = bp[tq + 4];
            }
            #pragma unroll
            for (int m = 0; m < 2; m++)
                #pragma unroll
                for (int n = 0; n < 12; n++)
                    mma_tf32(c[m][n], a[m], b[n]);
        }
        __syncthreads();
    }

    // ---- epilogue: bias + ReLU, float2 stores
    #pragma unroll
    for (int m = 0; m < 2; m++) {
        int row0 = rowBase + warp * 32 + m * 16 + g;
        int row1 = row0 + 8;
        #pragma unroll
        for (int n = 0; n < 12; n++) {
            int col = n * 8 + tq * 2;
            float bb0 = bls[col], bb1 = bls[col + 1];
            if (row0 < N_NODES) {
                float2 r0 = make_float2(fmaxf(c[m][n][0] + bb0, 0.f),
                                        fmaxf(c[m][n][1] + bb1, 0.f));
                *reinterpret_cast<float2*>(out + (size_t)row0 * D + col) = r0;
            }
            if (row1 < N_NODES) {
                float2 r1 = make_float2(fmaxf(c[m][n][2] + bb0, 0.f),
                                        fmaxf(c[m][n][3] + bb1, 0.f));
                *reinterpret_cast<float2*>(out + (size_t)row1 * D + col) = r1;
            }
        }
    }
}

// ---------------------------------------------------------------------------
extern "C" void kernel_launch(void* const* d_in, const int* in_sizes, int n_in,
                              void* d_out, int out_size) {
    const float* x  = (const float*)d_in[0];   // [N, 96]
    const int* ei   = (const int*)d_in[1];     // [2, E]
    const float* Wl = (const float*)d_in[2];   // [96, 96]
    const float* bl = (const float*)d_in[3];   // [96]
    const float* Wr = (const float*)d_in[4];   // [96, 96]
    float* out = (float*)d_out;                // [N, 96]

    cudaFuncSetAttribute(k_linear, cudaFuncAttributeMaxDynamicSharedMemorySize,
                         (int)SMEM_BYTES);

    void* cnt_ptr = nullptr;
    cudaGetSymbolAddress(&cnt_ptr, g_cnt);
    cudaMemsetAsync(cnt_ptr, 0, sizeof(int) * N_NODES);

    k_hist<<<(N_EDGES / 2 + 255) / 256, 256>>>(ei);
    k_scan1<<<NB, 256>>>();
    k_scatter<<<(N_EDGES + 255) / 256, 256>>>(ei);
    {
        int warps_per_block = 8;
        int blocks = (N_NODES + warps_per_block - 1) / warps_per_block;
        k_agg<<<blocks, warps_per_block * 32>>>(x, out);
    }
    k_linear<<<(N_NODES + 127) / 128, LTHREADS, SMEM_BYTES>>>(x, Wl, bl, Wr, out);
}